// round 14
// baseline (speedup 1.0000x reference)
#include <cuda_runtime.h>
#include <cuda_bf16.h>
#include <mma.h>
#include <cstdint>

using namespace nvcuda;

#define N_NODES 1024
#define N_EDGES 32768
#define KE 32
#define KOUT 32
#define DIN 64
#define DOUT 64
#define DNODE 64
#define KW 160
#define HID 256
#define N_TILES (N_EDGES / 128)   // 256 (edgex tiles)
#define ROWCAP 128

// -------- device scratch (static; no runtime allocation) --------
__device__ float g_h[N_NODES * DNODE];
__device__ float g_X4[N_EDGES * KE];
__device__ float g_X5[N_EDGES * KE];
__device__ float g_prod[N_EDGES * KE];
__device__ float g_path[N_EDGES * KE];
__device__ int   g_eid[N_NODES * N_NODES];    // BSS-zeroed; stores e+1, 0 = empty
__device__ int   g_rowcnt[N_NODES];
__device__ int   g_rowedges[N_NODES * ROWCAP];  // packed: (dst << 15) | e
__device__ float g_AGG[N_NODES * KOUT * DIN];

__device__ __align__(16) __nv_bfloat16 g_W6h[HID * KW];
__device__ __align__(16) __nv_bfloat16 g_W6l[HID * KW];
__device__ __align__(16) __nv_bfloat16 g_W7h[KOUT * HID];
__device__ __align__(16) __nv_bfloat16 g_W7l[KOUT * HID];
__device__ __align__(16) __nv_bfloat16 g_W25h[128 * KE];
__device__ __align__(16) __nv_bfloat16 g_W25l[128 * KE];

__device__ __forceinline__ void bf16_split(float v, __nv_bfloat16& h, __nv_bfloat16& l) {
    h = __float2bfloat16(v);
    l = __float2bfloat16(v - __bfloat162float(h));
}

__device__ __forceinline__ void pack4(__nv_bfloat16* H, __nv_bfloat16* L, int idx, float4 v) {
    __nv_bfloat16 h0, h1, h2, h3, l0, l1, l2, l3;
    bf16_split(v.x, h0, l0); bf16_split(v.y, h1, l1);
    bf16_split(v.z, h2, l2); bf16_split(v.w, h3, l3);
    __nv_bfloat162* ph = (__nv_bfloat162*)&H[idx];
    __nv_bfloat162* pl = (__nv_bfloat162*)&L[idx];
    __nv_bfloat162 a; a.x = h0; a.y = h1; ph[0] = a;
    __nv_bfloat162 b; b.x = h2; b.y = h3; ph[1] = b;
    __nv_bfloat162 c; c.x = l0; c.y = l1; pl[0] = c;
    __nv_bfloat162 d; d.x = l2; d.y = l3; pl[1] = d;
}

// ---------------- k_prep ----------------
#define NB_H    128
#define NB_W    104
#define NB_PREP (NB_H + NB_W + 2)

__global__ __launch_bounds__(512) void k_prep(const float* __restrict__ x,
                                              const float* __restrict__ Wnode,
                                              const float* __restrict__ W6,
                                              const float* __restrict__ W7,
                                              const float* __restrict__ W2,
                                              const float* __restrict__ W3,
                                              const float* __restrict__ W4,
                                              const float* __restrict__ W5) {
    int b = blockIdx.x;
    int t = threadIdx.x;
    if (b < NB_H) {
        __shared__ float ws[DNODE][DIN + 1];
        __shared__ float xs[8][DIN];
        for (int i = t; i < DNODE * DIN; i += 512) ws[i >> 6][i & 63] = Wnode[i];
        int nb = b * 8;
        int sub = t >> 6, c = t & 63;
        xs[sub][c] = x[(nb + sub) * DIN + c];
        __syncthreads();
        float acc = 0.f;
#pragma unroll
        for (int j = 0; j < DIN; j++) acc += xs[sub][j] * ws[c][j];
        g_h[(nb + sub) * DNODE + c] = acc;
    } else if (b < NB_H + NB_W) {
        int i = (b - NB_H) * 512 + t;
        if (i < HID * KW) {
            __nv_bfloat16 h, l;
            bf16_split(W6[i], h, l);
            g_W6h[i] = h; g_W6l[i] = l;
        } else if (i < HID * KW + KOUT * HID) {
            int j = i - HID * KW;
            __nv_bfloat16 h, l;
            bf16_split(W7[j], h, l);
            g_W7h[j] = h; g_W7l[j] = l;
        } else if (i < HID * KW + KOUT * HID + 128 * KE) {
            int j = i - (HID * KW + KOUT * HID);
            int m = j >> 10, r = j & 1023;
            const float* Ws = (m == 0) ? W2 : (m == 1) ? W3 : (m == 2) ? W4 : W5;
            __nv_bfloat16 h, l;
            bf16_split(Ws[r], h, l);
            g_W25h[j] = h; g_W25l[j] = l;
        }
    } else {
        int i = (b - NB_H - NB_W) * 512 + t;
        if (i < N_NODES) g_rowcnt[i] = 0;
    }
}

// ---- WMMA batched small GEMM + edge-table build ----
#define EX_SP_LD 40
#define EX_W_LD  40
#define EX_P_LD  36
#define EXOFF_SPH 0
#define EXOFF_SPL (EXOFF_SPH + 128 * EX_SP_LD * 2)
#define EXOFF_WH  (EXOFF_SPL + 128 * EX_SP_LD * 2)
#define EXOFF_WL  (EXOFF_WH + 128 * EX_W_LD * 2)
#define EXOFF_P2  (EXOFF_WL + 128 * EX_W_LD * 2)
#define EXOFF_P3  (EXOFF_P2 + 128 * EX_P_LD * 4)
#define SMEM_EDGEX (EXOFF_P3 + 128 * EX_P_LD * 4)     // 77824

__global__ __launch_bounds__(256, 1) void k_edgex(const float* __restrict__ SP,
                                                  const int* __restrict__ ei) {
    extern __shared__ char S[];
    int t = threadIdx.x;
    int w = t >> 5;
    int tile = blockIdx.x;

    if (t < 128) {
        int e = tile * 128 + t;
        int s = ei[e], d = ei[N_EDGES + e];
        g_eid[s * N_NODES + d] = e + 1;
        int pos = atomicAdd(&g_rowcnt[s], 1);
        g_rowedges[s * ROWCAP + pos] = e | (d << 15);
    }

    __nv_bfloat16* sSPh = (__nv_bfloat16*)(S + EXOFF_SPH);
    __nv_bfloat16* sSPl = (__nv_bfloat16*)(S + EXOFF_SPL);
    __nv_bfloat16* sWh  = (__nv_bfloat16*)(S + EXOFF_WH);
    __nv_bfloat16* sWl  = (__nv_bfloat16*)(S + EXOFF_WL);
    float* P2 = (float*)(S + EXOFF_P2);
    float* P3 = (float*)(S + EXOFF_P3);

    for (int i = t; i < 1024; i += 256) {
        int r = i >> 3, c4 = (i & 7) << 2;
        pack4(sSPh, sSPl, r * EX_SP_LD + c4, *(const float4*)&SP[(size_t)(tile * 128 + r) * KE + c4]);
    }
    for (int i = t; i < 512; i += 256) {
        int r = i >> 2, sg = (i & 3) << 3;
        *(uint4*)&sWh[r * EX_W_LD + sg] = *(const uint4*)&g_W25h[r * KE + sg];
        *(uint4*)&sWl[r * EX_W_LD + sg] = *(const uint4*)&g_W25l[r * KE + sg];
    }
    __syncthreads();

    wmma::fragment<wmma::matrix_a, 16, 16, 16, __nv_bfloat16, wmma::row_major> ah[2], al[2];
#pragma unroll
    for (int kf = 0; kf < 2; kf++) {
        wmma::load_matrix_sync(ah[kf], sSPh + w * 16 * EX_SP_LD + kf * 16, EX_SP_LD);
        wmma::load_matrix_sync(al[kf], sSPl + w * 16 * EX_SP_LD + kf * 16, EX_SP_LD);
    }
#pragma unroll
    for (int nf = 0; nf < 8; nf++) {
        wmma::fragment<wmma::accumulator, 16, 16, 16, float> acc;
        wmma::fill_fragment(acc, 0.f);
#pragma unroll
        for (int kf = 0; kf < 2; kf++) {
            wmma::fragment<wmma::matrix_b, 16, 16, 16, __nv_bfloat16, wmma::col_major> bh, bl;
            wmma::load_matrix_sync(bh, sWh + nf * 16 * EX_W_LD + kf * 16, EX_W_LD);
            wmma::load_matrix_sync(bl, sWl + nf * 16 * EX_W_LD + kf * 16, EX_W_LD);
            wmma::mma_sync(acc, ah[kf], bh, acc);
            wmma::mma_sync(acc, ah[kf], bl, acc);
            wmma::mma_sync(acc, al[kf], bh, acc);
        }
        if (nf < 2) {
            wmma::store_matrix_sync(P2 + w * 16 * EX_P_LD + nf * 16, acc, EX_P_LD, wmma::mem_row_major);
        } else if (nf < 4) {
            wmma::store_matrix_sync(P3 + w * 16 * EX_P_LD + (nf - 2) * 16, acc, EX_P_LD, wmma::mem_row_major);
        } else if (nf < 6) {
            wmma::store_matrix_sync(g_X4 + (size_t)(tile * 128 + w * 16) * KE + (nf - 4) * 16,
                                    acc, KE, wmma::mem_row_major);
        } else {
            wmma::store_matrix_sync(g_X5 + (size_t)(tile * 128 + w * 16) * KE + (nf - 6) * 16,
                                    acc, KE, wmma::mem_row_major);
        }
    }
    __syncthreads();
    for (int i = t; i < 4096; i += 256) {
        int r = i >> 5, c = i & 31;
        g_prod[(size_t)(tile * 128 + r) * KE + c] = P2[r * EX_P_LD + c] * P3[r * EX_P_LD + c];
    }
}

// ---------------- per-node sampled sparse-sparse matmul -> g_path ----------------
__global__ __launch_bounds__(256) void k_path() {
    __shared__ int el[ROWCAP];
    __shared__ int dl[ROWCAP];
    __shared__ float x4s[ROWCAP * KE];   // 16 KB
    int i = blockIdx.x;
    int t = threadIdx.x, w = t >> 5, lane = t & 31;
    int deg = g_rowcnt[i];
    for (int m = t; m < deg; m += 256) {
        int pk = g_rowedges[i * ROWCAP + m];
        el[m] = pk & 0x7FFF;
        dl[m] = pk >> 15;
    }
    __syncthreads();
    for (int idx = t; idx < deg * KE; idx += 256) {
        int m = idx >> 5, k = idx & 31;
        x4s[m * KE + k] = g_X4[(size_t)el[m] * KE + k];
    }
    __syncthreads();
    for (int tt = w; tt < deg; tt += 8) {
        int j = dl[tt];
        float acc = 0.f;
        for (int s = 0; s < deg; s += 32) {
            int m = s + lane;
            int e2 = -1;
            if (m < deg) e2 = g_eid[dl[m] * N_NODES + j] - 1;
            unsigned mask = __ballot_sync(0xFFFFFFFFu, e2 >= 0);
            while (mask) {
                int b = __ffs(mask) - 1;
                mask &= mask - 1;
                int M = s + b;
                int E2 = __shfl_sync(0xFFFFFFFFu, e2, b);
                acc += x4s[M * KE + lane] * g_X5[(size_t)E2 * KE + lane];
            }
        }
        g_path[(size_t)el[tt] * KE + lane] = acc;
    }
}

// ---------------- fused WMMA edge MLP (64-row tiles, 512 thr, 2 CTAs/SM) ----------------
#define FM      64
#define FGRID   (N_EDGES / FM)     // 512
#define AS_LD   168
#define W6S_LD  168
#define W7S_LD  72
#define HS_LD   72
#define OFF_AH  0
#define OFF_AL  (OFF_AH + FM * AS_LD * 2)            // 21504
#define OFF_W6H (OFF_AL + FM * AS_LD * 2)            // 43008
#define OFF_W6L (OFF_W6H + 64 * W6S_LD * 2)          // 64512
#define OFF_W7H (OFF_W6L + 64 * W6S_LD * 2)          // 86016
#define OFF_W7L (OFF_W7H + 32 * W7S_LD * 2)          // 90624
#define OFF_HH  (OFF_W7L + 32 * W7S_LD * 2)          // 95232
#define OFF_HL  (OFF_HH + FM * HS_LD * 2)            // 104448
#define SMEM_FUSED (OFF_HL + FM * HS_LD * 2)         // 113664
#define OFF_CBUF OFF_W6H                              // fp32 64x68 = 17408 (< W6 region)
#define CB_LD   68
#define EB_LD   36

__global__ __launch_bounds__(512, 2) void k_fused(const float* __restrict__ SP,
                                                  const int* __restrict__ ei,
                                                  float* __restrict__ EA) {
    extern __shared__ char S[];
    int t = threadIdx.x;
    int w = t >> 5, lane = t & 31;
    int wm = w >> 2, wn = w & 3;       // 4 M-subtiles x 4 N-subtiles (16 warps)
    int tile = blockIdx.x;

    __nv_bfloat16* sAh  = (__nv_bfloat16*)(S + OFF_AH);
    __nv_bfloat16* sAl  = (__nv_bfloat16*)(S + OFF_AL);
    __nv_bfloat16* sW6h = (__nv_bfloat16*)(S + OFF_W6H);
    __nv_bfloat16* sW6l = (__nv_bfloat16*)(S + OFF_W6L);
    __nv_bfloat16* sW7h = (__nv_bfloat16*)(S + OFF_W7H);
    __nv_bfloat16* sW7l = (__nv_bfloat16*)(S + OFF_W7L);
    __nv_bfloat16* sHh  = (__nv_bfloat16*)(S + OFF_HH);
    __nv_bfloat16* sHl  = (__nv_bfloat16*)(S + OFF_HL);
    float* Cbuf = (float*)(S + OFF_CBUF);

    // ---- assemble A tile [64 x 160] bf16 hi/lo ----
    for (int i = t; i < FM * 8; i += 512) {           // 64 rows x 8 float4
        int r = i >> 3, c4 = (i & 7) << 2;
        size_t g = (size_t)(tile * FM + r) * KE + c4;
        pack4(sAh, sAl, r * AS_LD + c4, *(const float4*)&SP[g]);
        pack4(sAh, sAl, r * AS_LD + 32 + c4, *(const float4*)&g_prod[g]);
        pack4(sAh, sAl, r * AS_LD + 128 + c4, *(const float4*)&g_path[g]);
    }
    for (int i = t; i < FM * 32; i += 512) {          // zero diag cols [64:128)
        int r = i >> 5, u = i & 31;
        ((uint32_t*)&sAh[r * AS_LD + 64])[u] = 0u;
        ((uint32_t*)&sAl[r * AS_LD + 64])[u] = 0u;
    }
    __syncthreads();
    if (t < FM) {
        int e = tile * FM + t;
        int si = ei[e], dj = ei[N_EDGES + e];
        if (si == dj) {
            for (int c = 0; c < 64; c++) {
                __nv_bfloat16 h, l;
                bf16_split(g_h[si * DNODE + c], h, l);
                sAh[t * AS_LD + 64 + c] = h;
                sAl[t * AS_LD + 64 + c] = l;
            }
        }
    }

    wmma::fragment<wmma::accumulator, 16, 16, 16, float> ea;
    wmma::fill_fragment(ea, 0.f);

    for (int nc = 0; nc < 4; nc++) {
        __syncthreads();   // A/diag ready (nc=0); Cbuf consumed (nc>0)
        // load W6 chunk [64 x 160] and W7 chunk [32 x 64]
        {
            const uint4* bH = (const uint4*)(g_W6h + (size_t)nc * 64 * KW);
            const uint4* bL = (const uint4*)(g_W6l + (size_t)nc * 64 * KW);
            for (int i = t; i < 64 * 20; i += 512) {
                int r = i / 20, sgi = i % 20;
                *(uint4*)&sW6h[r * W6S_LD + sgi * 8] = bH[i];
                *(uint4*)&sW6l[r * W6S_LD + sgi * 8] = bL[i];
            }
            if (t < 256) {
                int r = t >> 3, sg = t & 7;
                *(uint4*)&sW7h[r * W7S_LD + sg * 8] = *(const uint4*)&g_W7h[r * HID + nc * 64 + sg * 8];
                *(uint4*)&sW7l[r * W7S_LD + sg * 8] = *(const uint4*)&g_W7l[r * HID + nc * 64 + sg * 8];
            }
        }
        __syncthreads();

        // GEMM1 chunk: C[64,64]; warp (wm,wn) -> 16x16 tile
        wmma::fragment<wmma::accumulator, 16, 16, 16, float> c;
        wmma::fill_fragment(c, 0.f);
#pragma unroll
        for (int k = 0; k < 10; k++) {
            wmma::fragment<wmma::matrix_a, 16, 16, 16, __nv_bfloat16, wmma::row_major> ah, al;
            wmma::load_matrix_sync(ah, sAh + wm * 16 * AS_LD + k * 16, AS_LD);
            wmma::load_matrix_sync(al, sAl + wm * 16 * AS_LD + k * 16, AS_LD);
            wmma::fragment<wmma::matrix_b, 16, 16, 16, __nv_bfloat16, wmma::col_major> bh, bl;
            wmma::load_matrix_sync(bh, sW6h + wn * 16 * W6S_LD + k * 16, W6S_LD);
            wmma::load_matrix_sync(bl, sW6l + wn * 16 * W6S_LD + k * 16, W6S_LD);
            wmma::mma_sync(c, ah, bh, c);
            wmma::mma_sync(c, ah, bl, c);
            wmma::mma_sync(c, al, bh, c);
        }
        __syncthreads();   // all warps done reading W6 chunk; Cbuf region free

        // store fp32 C piece, relu + split -> H (warp-local 16x16)
        wmma::store_matrix_sync(Cbuf + wm * 16 * CB_LD + wn * 16, c, CB_LD, wmma::mem_row_major);
        __syncwarp();
#pragma unroll
        for (int idx = 0; idx < 8; idx++) {
            int f = lane + idx * 32;           // 0..255 : 16 rows x 16 cols
            int r = f >> 4, cc = f & 15;
            float v = fmaxf(Cbuf[(wm * 16 + r) * CB_LD + wn * 16 + cc], 0.f);
            __nv_bfloat16 h, l;
            bf16_split(v, h, l);
            sHh[(wm * 16 + r) * HS_LD + wn * 16 + cc] = h;
            sHl[(wm * 16 + r) * HS_LD + wn * 16 + cc] = l;
        }
        __syncthreads();   // H chunk complete

        // GEMM2 partial (warps wn<2): ea += Hc[16,64] @ W7c^T ; cols wn*16
        if (wn < 2) {
#pragma unroll
            for (int k2 = 0; k2 < 4; k2++) {
                wmma::fragment<wmma::matrix_a, 16, 16, 16, __nv_bfloat16, wmma::row_major> ah, al;
                wmma::load_matrix_sync(ah, sHh + wm * 16 * HS_LD + k2 * 16, HS_LD);
                wmma::load_matrix_sync(al, sHl + wm * 16 * HS_LD + k2 * 16, HS_LD);
                wmma::fragment<wmma::matrix_b, 16, 16, 16, __nv_bfloat16, wmma::col_major> bh, bl;
                wmma::load_matrix_sync(bh, sW7h + wn * 16 * W7S_LD + k2 * 16, W7S_LD);
                wmma::load_matrix_sync(bl, sW7l + wn * 16 * W7S_LD + k2 * 16, W7S_LD);
                wmma::mma_sync(ea, ah, bh, ea);
                wmma::mma_sync(ea, ah, bl, ea);
                wmma::mma_sync(ea, al, bh, ea);
            }
        }
    }

    // epilogue
    __syncthreads();
    float* Ebuf = Cbuf;                        // 64 x 36 fp32
    if (wn < 2)
        wmma::store_matrix_sync(Ebuf + wm * 16 * EB_LD + wn * 16, ea, EB_LD, wmma::mem_row_major);
    __syncthreads();
    if (t < FM * 8) {                          // 512 threads -> one float4 each
        int r = t >> 3, sgi = t & 7;
        float4 v = *(float4*)&Ebuf[r * EB_LD + sgi * 4];
        *(float4*)&EA[((size_t)tile * FM + r) * KOUT + sgi * 4] = v;
    }
}

// ---------------- aggregation + output ----------------
__global__ void k_agg(const float* __restrict__ x, const int* __restrict__ ei,
                      const float* __restrict__ EA) {
    int i = blockIdx.x;
    int t = threadIdx.x;  // 256
    __shared__ float ea_b[8][33];
    __shared__ float x_b[8][64];
    __shared__ int elist[8], dlist[8];
    float acc[8];
#pragma unroll
    for (int q = 0; q < 8; q++) acc[q] = 0.f;
    int start = i * ROWCAP;
    int end = start + g_rowcnt[i];
    int c = t & 63, k0 = t >> 6;
    for (int p = start; p < end; p += 8) {
        int nb = min(8, end - p);
        if (t < nb) {
            int pk = g_rowedges[p + t];
            elist[t] = pk & 0x7FFF;
            dlist[t] = pk >> 15;
        }
        __syncthreads();
        for (int i2 = t; i2 < nb * 96; i2 += 256) {
            int b = i2 / 96, f = i2 % 96;
            if (f < 32) ea_b[b][f] = EA[(size_t)elist[b] * KOUT + f];
            else x_b[b][f - 32] = x[dlist[b] * DIN + f - 32];
        }
        __syncthreads();
        for (int b = 0; b < nb; b++) {
            float xv = x_b[b][c];
#pragma unroll
            for (int q = 0; q < 8; q++) acc[q] += ea_b[b][k0 + q * 4] * xv;
        }
        __syncthreads();
    }
#pragma unroll
    for (int q = 0; q < 8; q++) g_AGG[i * (KOUT * DIN) + t + q * 256] = acc[q];
}

__global__ void k_out(const float* __restrict__ CW, const float* __restrict__ CB,
                      float* __restrict__ xout) {
    __shared__ float As[32][32];
    __shared__ float Bs[32][68];
    int t = threadIdx.x;
    int tx = t & 15, ty = t >> 4;
    int rowBase = blockIdx.x * 32;
    const int KTOT = KOUT * DIN;
    float acc[2][4] = {};
    for (int k0 = 0; k0 < KTOT; k0 += 32) {
        {
            int r = t >> 3, kk = (t & 7) << 2;
            float4 v = *(const float4*)&g_AGG[(rowBase + r) * KTOT + k0 + kk];
            *(float4*)&As[r][kk] = v;
        }
#pragma unroll
        for (int l = 0; l < 2; l++) {
            int fid = t + l * 256;
            int kk = fid >> 4, n4 = (fid & 15) << 2;
            float4 v = *(const float4*)&CW[(k0 + kk) * DOUT + n4];
            *(float4*)&Bs[kk][n4] = v;
        }
        __syncthreads();
#pragma unroll
        for (int kk = 0; kk < 32; kk++) {
            float a[2], b[4];
            a[0] = As[ty * 2][kk]; a[1] = As[ty * 2 + 1][kk];
            float4 bv = *(const float4*)&Bs[kk][tx * 4];
            b[0] = bv.x; b[1] = bv.y; b[2] = bv.z; b[3] = bv.w;
#pragma unroll
            for (int i = 0; i < 2; i++)
#pragma unroll
                for (int j = 0; j < 4; j++) acc[i][j] += a[i] * b[j];
        }
        __syncthreads();
    }
#pragma unroll
    for (int i = 0; i < 2; i++) {
        int r = rowBase + ty * 2 + i;
#pragma unroll
        for (int j = 0; j < 4; j++)
            xout[r * DOUT + tx * 4 + j] = acc[i][j] + CB[tx * 4 + j];
    }
}

// ---------------------------------------------------------------
extern "C" void kernel_launch(void* const* d_in, const int* in_sizes, int n_in,
                              void* d_out, int out_size) {
    const float* x     = (const float*)d_in[0];
    const int*   ei    = (const int*)  d_in[1];
    const float* SP    = (const float*)d_in[2];
    const float* Wnode = (const float*)d_in[4];
    const float* W2    = (const float*)d_in[5];
    const float* W3    = (const float*)d_in[6];
    const float* W4    = (const float*)d_in[7];
    const float* W5    = (const float*)d_in[8];
    const float* W6    = (const float*)d_in[9];
    const float* W7    = (const float*)d_in[10];
    const float* CW    = (const float*)d_in[11];
    const float* CB    = (const float*)d_in[12];

    float* xout = (float*)d_out;                       // [1024, 64]
    float* EA   = (float*)d_out + N_NODES * DOUT;      // [32768, 32]

    cudaFuncSetAttribute(k_fused, cudaFuncAttributeMaxDynamicSharedMemorySize, SMEM_FUSED);
    cudaFuncSetAttribute(k_edgex, cudaFuncAttributeMaxDynamicSharedMemorySize, SMEM_EDGEX);

    k_prep<<<NB_PREP, 512>>>(x, Wnode, W6, W7, W2, W3, W4, W5);   // 0
    k_edgex<<<N_TILES, 256, SMEM_EDGEX>>>(SP, ei);                // 1
    k_path<<<N_NODES, 256>>>();                                   // 2 (per-node)
    k_fused<<<FGRID, 512, SMEM_FUSED>>>(SP, ei, EA);              // 3
    k_agg<<<N_NODES, 256>>>(x, ei, EA);                           // 4
    k_out<<<N_NODES / 32, 256>>>(CW, CB, xout);                   // 5
}

// round 15
// speedup vs baseline: 1.0763x; 1.0763x over previous
#include <cuda_runtime.h>
#include <cuda_bf16.h>
#include <mma.h>
#include <cstdint>

using namespace nvcuda;

#define N_NODES 1024
#define N_EDGES 32768
#define KE 32
#define KOUT 32
#define DIN 64
#define DOUT 64
#define DNODE 64
#define KW 160
#define HID 256
#define N_TILES (N_EDGES / 128)   // 256 (edgex tiles)
#define ROWCAP 128

// -------- device scratch (static; no runtime allocation) --------
__device__ float g_h[N_NODES * DNODE];
__device__ float g_X4[N_EDGES * KE];
__device__ float g_X5[N_EDGES * KE];
__device__ float g_prod[N_EDGES * KE];
__device__ float g_path[N_EDGES * KE];
__device__ int   g_eid[N_NODES * N_NODES];    // BSS-zeroed; stores e+1, 0 = empty
__device__ int   g_rowcnt[N_NODES];
__device__ int   g_rowedges[N_NODES * ROWCAP];  // packed: (dst << 15) | e
__device__ float g_AGG[N_NODES * KOUT * DIN];

__device__ __align__(16) __nv_bfloat16 g_W6h[HID * KW];
__device__ __align__(16) __nv_bfloat16 g_W6l[HID * KW];
__device__ __align__(16) __nv_bfloat16 g_W7h[KOUT * HID];
__device__ __align__(16) __nv_bfloat16 g_W7l[KOUT * HID];
__device__ __align__(16) __nv_bfloat16 g_W25h[128 * KE];
__device__ __align__(16) __nv_bfloat16 g_W25l[128 * KE];

__device__ __forceinline__ void bf16_split(float v, __nv_bfloat16& h, __nv_bfloat16& l) {
    h = __float2bfloat16(v);
    l = __float2bfloat16(v - __bfloat162float(h));
}

__device__ __forceinline__ void pack4(__nv_bfloat16* H, __nv_bfloat16* L, int idx, float4 v) {
    __nv_bfloat16 h0, h1, h2, h3, l0, l1, l2, l3;
    bf16_split(v.x, h0, l0); bf16_split(v.y, h1, l1);
    bf16_split(v.z, h2, l2); bf16_split(v.w, h3, l3);
    __nv_bfloat162* ph = (__nv_bfloat162*)&H[idx];
    __nv_bfloat162* pl = (__nv_bfloat162*)&L[idx];
    __nv_bfloat162 a; a.x = h0; a.y = h1; ph[0] = a;
    __nv_bfloat162 b; b.x = h2; b.y = h3; ph[1] = b;
    __nv_bfloat162 c; c.x = l0; c.y = l1; pl[0] = c;
    __nv_bfloat162 d; d.x = l2; d.y = l3; pl[1] = d;
}

// ---------------- k_prep ----------------
#define NB_H    128
#define NB_W    104
#define NB_PREP (NB_H + NB_W + 2)

__global__ __launch_bounds__(512) void k_prep(const float* __restrict__ x,
                                              const float* __restrict__ Wnode,
                                              const float* __restrict__ W6,
                                              const float* __restrict__ W7,
                                              const float* __restrict__ W2,
                                              const float* __restrict__ W3,
                                              const float* __restrict__ W4,
                                              const float* __restrict__ W5) {
    int b = blockIdx.x;
    int t = threadIdx.x;
    if (b < NB_H) {
        __shared__ float ws[DNODE][DIN + 1];
        __shared__ float xs[8][DIN];
        for (int i = t; i < DNODE * DIN; i += 512) ws[i >> 6][i & 63] = Wnode[i];
        int nb = b * 8;
        int sub = t >> 6, c = t & 63;
        xs[sub][c] = x[(nb + sub) * DIN + c];
        __syncthreads();
        float acc = 0.f;
#pragma unroll
        for (int j = 0; j < DIN; j++) acc += xs[sub][j] * ws[c][j];
        g_h[(nb + sub) * DNODE + c] = acc;
    } else if (b < NB_H + NB_W) {
        int i = (b - NB_H) * 512 + t;
        if (i < HID * KW) {
            __nv_bfloat16 h, l;
            bf16_split(W6[i], h, l);
            g_W6h[i] = h; g_W6l[i] = l;
        } else if (i < HID * KW + KOUT * HID) {
            int j = i - HID * KW;
            __nv_bfloat16 h, l;
            bf16_split(W7[j], h, l);
            g_W7h[j] = h; g_W7l[j] = l;
        } else if (i < HID * KW + KOUT * HID + 128 * KE) {
            int j = i - (HID * KW + KOUT * HID);
            int m = j >> 10, r = j & 1023;
            const float* Ws = (m == 0) ? W2 : (m == 1) ? W3 : (m == 2) ? W4 : W5;
            __nv_bfloat16 h, l;
            bf16_split(Ws[r], h, l);
            g_W25h[j] = h; g_W25l[j] = l;
        }
    } else {
        int i = (b - NB_H - NB_W) * 512 + t;
        if (i < N_NODES) g_rowcnt[i] = 0;
    }
}

// ---- WMMA batched small GEMM + edge-table build ----
#define EX_SP_LD 40
#define EX_W_LD  40
#define EX_P_LD  36
#define EXOFF_SPH 0
#define EXOFF_SPL (EXOFF_SPH + 128 * EX_SP_LD * 2)
#define EXOFF_WH  (EXOFF_SPL + 128 * EX_SP_LD * 2)
#define EXOFF_WL  (EXOFF_WH + 128 * EX_W_LD * 2)
#define EXOFF_P2  (EXOFF_WL + 128 * EX_W_LD * 2)
#define EXOFF_P3  (EXOFF_P2 + 128 * EX_P_LD * 4)
#define SMEM_EDGEX (EXOFF_P3 + 128 * EX_P_LD * 4)     // 77824

__global__ __launch_bounds__(256, 1) void k_edgex(const float* __restrict__ SP,
                                                  const int* __restrict__ ei) {
    extern __shared__ char S[];
    int t = threadIdx.x;
    int w = t >> 5;
    int tile = blockIdx.x;

    if (t < 128) {
        int e = tile * 128 + t;
        int s = ei[e], d = ei[N_EDGES + e];
        g_eid[s * N_NODES + d] = e + 1;
        int pos = atomicAdd(&g_rowcnt[s], 1);
        g_rowedges[s * ROWCAP + pos] = e | (d << 15);
    }

    __nv_bfloat16* sSPh = (__nv_bfloat16*)(S + EXOFF_SPH);
    __nv_bfloat16* sSPl = (__nv_bfloat16*)(S + EXOFF_SPL);
    __nv_bfloat16* sWh  = (__nv_bfloat16*)(S + EXOFF_WH);
    __nv_bfloat16* sWl  = (__nv_bfloat16*)(S + EXOFF_WL);
    float* P2 = (float*)(S + EXOFF_P2);
    float* P3 = (float*)(S + EXOFF_P3);

    for (int i = t; i < 1024; i += 256) {
        int r = i >> 3, c4 = (i & 7) << 2;
        pack4(sSPh, sSPl, r * EX_SP_LD + c4, *(const float4*)&SP[(size_t)(tile * 128 + r) * KE + c4]);
    }
    for (int i = t; i < 512; i += 256) {
        int r = i >> 2, sg = (i & 3) << 3;
        *(uint4*)&sWh[r * EX_W_LD + sg] = *(const uint4*)&g_W25h[r * KE + sg];
        *(uint4*)&sWl[r * EX_W_LD + sg] = *(const uint4*)&g_W25l[r * KE + sg];
    }
    __syncthreads();

    wmma::fragment<wmma::matrix_a, 16, 16, 16, __nv_bfloat16, wmma::row_major> ah[2], al[2];
#pragma unroll
    for (int kf = 0; kf < 2; kf++) {
        wmma::load_matrix_sync(ah[kf], sSPh + w * 16 * EX_SP_LD + kf * 16, EX_SP_LD);
        wmma::load_matrix_sync(al[kf], sSPl + w * 16 * EX_SP_LD + kf * 16, EX_SP_LD);
    }
#pragma unroll
    for (int nf = 0; nf < 8; nf++) {
        wmma::fragment<wmma::accumulator, 16, 16, 16, float> acc;
        wmma::fill_fragment(acc, 0.f);
#pragma unroll
        for (int kf = 0; kf < 2; kf++) {
            wmma::fragment<wmma::matrix_b, 16, 16, 16, __nv_bfloat16, wmma::col_major> bh, bl;
            wmma::load_matrix_sync(bh, sWh + nf * 16 * EX_W_LD + kf * 16, EX_W_LD);
            wmma::load_matrix_sync(bl, sWl + nf * 16 * EX_W_LD + kf * 16, EX_W_LD);
            wmma::mma_sync(acc, ah[kf], bh, acc);
            wmma::mma_sync(acc, ah[kf], bl, acc);
            wmma::mma_sync(acc, al[kf], bh, acc);
        }
        if (nf < 2) {
            wmma::store_matrix_sync(P2 + w * 16 * EX_P_LD + nf * 16, acc, EX_P_LD, wmma::mem_row_major);
        } else if (nf < 4) {
            wmma::store_matrix_sync(P3 + w * 16 * EX_P_LD + (nf - 2) * 16, acc, EX_P_LD, wmma::mem_row_major);
        } else if (nf < 6) {
            wmma::store_matrix_sync(g_X4 + (size_t)(tile * 128 + w * 16) * KE + (nf - 4) * 16,
                                    acc, KE, wmma::mem_row_major);
        } else {
            wmma::store_matrix_sync(g_X5 + (size_t)(tile * 128 + w * 16) * KE + (nf - 6) * 16,
                                    acc, KE, wmma::mem_row_major);
        }
    }
    __syncthreads();
    for (int i = t; i < 4096; i += 256) {
        int r = i >> 5, c = i & 31;
        g_prod[(size_t)(tile * 128 + r) * KE + c] = P2[r * EX_P_LD + c] * P3[r * EX_P_LD + c];
    }
}

// sampled sparse-sparse matmul -> g_path (per-edge, R12 version)
__global__ void k_path(const int* __restrict__ ei) {
    int warp = (blockIdx.x * blockDim.x + threadIdx.x) >> 5;
    int lane = threadIdx.x & 31;
    if (warp >= N_EDGES) return;
    int e = warp;
    int i = ei[e], j = ei[N_EDGES + e];
    int start = i * ROWCAP;
    int end = start + g_rowcnt[i];
    float acc = 0.f;
    for (int s = start; s < end; s += 32) {
        int idx = s + lane;
        int e1 = -1, e2 = -1;
        if (idx < end) {
            int p = g_rowedges[idx];
            e1 = p & 0x7FFF;
            e2 = g_eid[(p >> 15) * N_NODES + j] - 1;
        }
        unsigned mask = __ballot_sync(0xFFFFFFFFu, e2 >= 0);
        while (mask) {
            int b = __ffs(mask) - 1;
            mask &= mask - 1;
            int E1 = __shfl_sync(0xFFFFFFFFu, e1, b);
            int E2 = __shfl_sync(0xFFFFFFFFu, e2, b);
            acc += g_X4[E1 * KE + lane] * g_X5[E2 * KE + lane];
        }
    }
    g_path[(size_t)e * KE + lane] = acc;
}

// ---------------- fused WMMA edge MLP (64-row tiles, 128 thr, 32x32 warp tiles, 2 CTAs/SM) ----------------
#define FM      64
#define FGRID   (N_EDGES / FM)     // 512
#define AS_LD   168
#define W6S_LD  168
#define W7S_LD  72
#define HS_LD   72
#define OFF_AH  0
#define OFF_AL  (OFF_AH + FM * AS_LD * 2)            // 21504
#define OFF_W6H (OFF_AL + FM * AS_LD * 2)            // 43008
#define OFF_W6L (OFF_W6H + 64 * W6S_LD * 2)          // 64512
#define OFF_W7H (OFF_W6L + 64 * W6S_LD * 2)          // 86016
#define OFF_W7L (OFF_W7H + 32 * W7S_LD * 2)          // 90624
#define OFF_HH  (OFF_W7L + 32 * W7S_LD * 2)          // 95232
#define OFF_HL  (OFF_HH + FM * HS_LD * 2)            // 104448
#define SMEM_FUSED (OFF_HL + FM * HS_LD * 2)         // 113664
#define OFF_CBUF OFF_W6H                              // fp32 64x68 = 17408 (< W6 region)
#define CB_LD   68
#define EB_LD   36

__global__ __launch_bounds__(128, 2) void k_fused(const float* __restrict__ SP,
                                                  const int* __restrict__ ei,
                                                  float* __restrict__ EA) {
    extern __shared__ char S[];
    int t = threadIdx.x;
    int w = t >> 5, lane = t & 31;
    int wm = w >> 1, wn = w & 1;       // 2 M-subtiles x 2 N-subtiles (32x32 each)
    int tile = blockIdx.x;

    __nv_bfloat16* sAh  = (__nv_bfloat16*)(S + OFF_AH);
    __nv_bfloat16* sAl  = (__nv_bfloat16*)(S + OFF_AL);
    __nv_bfloat16* sW6h = (__nv_bfloat16*)(S + OFF_W6H);
    __nv_bfloat16* sW6l = (__nv_bfloat16*)(S + OFF_W6L);
    __nv_bfloat16* sW7h = (__nv_bfloat16*)(S + OFF_W7H);
    __nv_bfloat16* sW7l = (__nv_bfloat16*)(S + OFF_W7L);
    __nv_bfloat16* sHh  = (__nv_bfloat16*)(S + OFF_HH);
    __nv_bfloat16* sHl  = (__nv_bfloat16*)(S + OFF_HL);
    float* Cbuf = (float*)(S + OFF_CBUF);

    // ---- assemble A tile [64 x 160] bf16 hi/lo ----
    for (int i = t; i < FM * 8; i += 128) {           // 64 rows x 8 float4
        int r = i >> 3, c4 = (i & 7) << 2;
        size_t g = (size_t)(tile * FM + r) * KE + c4;
        pack4(sAh, sAl, r * AS_LD + c4, *(const float4*)&SP[g]);
        pack4(sAh, sAl, r * AS_LD + 32 + c4, *(const float4*)&g_prod[g]);
        pack4(sAh, sAl, r * AS_LD + 128 + c4, *(const float4*)&g_path[g]);
    }
    for (int i = t; i < FM * 32; i += 128) {          // zero diag cols [64:128)
        int r = i >> 5, u = i & 31;
        ((uint32_t*)&sAh[r * AS_LD + 64])[u] = 0u;
        ((uint32_t*)&sAl[r * AS_LD + 64])[u] = 0u;
    }
    __syncthreads();
    if (t < FM) {
        int e = tile * FM + t;
        int si = ei[e], dj = ei[N_EDGES + e];
        if (si == dj) {
            for (int c = 0; c < 64; c++) {
                __nv_bfloat16 h, l;
                bf16_split(g_h[si * DNODE + c], h, l);
                sAh[t * AS_LD + 64 + c] = h;
                sAl[t * AS_LD + 64 + c] = l;
            }
        }
    }

    wmma::fragment<wmma::accumulator, 16, 16, 16, float> ea[2];
    wmma::fill_fragment(ea[0], 0.f);
    wmma::fill_fragment(ea[1], 0.f);

    for (int nc = 0; nc < 4; nc++) {
        __syncthreads();   // A/diag ready (nc=0); Cbuf consumed (nc>0)
        // load W6 chunk [64 x 160] and W7 chunk [32 x 64]
        {
            const uint4* bH = (const uint4*)(g_W6h + (size_t)nc * 64 * KW);
            const uint4* bL = (const uint4*)(g_W6l + (size_t)nc * 64 * KW);
            for (int i = t; i < 64 * 20; i += 128) {
                int r = i / 20, sgi = i % 20;
                *(uint4*)&sW6h[r * W6S_LD + sgi * 8] = bH[i];
                *(uint4*)&sW6l[r * W6S_LD + sgi * 8] = bL[i];
            }
            for (int i = t; i < 256; i += 128) {
                int r = i >> 3, sg = i & 7;
                *(uint4*)&sW7h[r * W7S_LD + sg * 8] = *(const uint4*)&g_W7h[r * HID + nc * 64 + sg * 8];
                *(uint4*)&sW7l[r * W7S_LD + sg * 8] = *(const uint4*)&g_W7l[r * HID + nc * 64 + sg * 8];
            }
        }
        __syncthreads();

        // GEMM1 chunk: C[64,64]; warp (wm,wn) -> 32x32 tile (2x2 fragment block)
        wmma::fragment<wmma::accumulator, 16, 16, 16, float> c[2][2];
#pragma unroll
        for (int mi = 0; mi < 2; mi++)
#pragma unroll
            for (int ni = 0; ni < 2; ni++) wmma::fill_fragment(c[mi][ni], 0.f);
#pragma unroll
        for (int k = 0; k < 10; k++) {
            wmma::fragment<wmma::matrix_a, 16, 16, 16, __nv_bfloat16, wmma::row_major> ah[2], al[2];
#pragma unroll
            for (int mi = 0; mi < 2; mi++) {
                wmma::load_matrix_sync(ah[mi], sAh + (wm * 32 + mi * 16) * AS_LD + k * 16, AS_LD);
                wmma::load_matrix_sync(al[mi], sAl + (wm * 32 + mi * 16) * AS_LD + k * 16, AS_LD);
            }
#pragma unroll
            for (int ni = 0; ni < 2; ni++) {
                wmma::fragment<wmma::matrix_b, 16, 16, 16, __nv_bfloat16, wmma::col_major> bh, bl;
                wmma::load_matrix_sync(bh, sW6h + (wn * 32 + ni * 16) * W6S_LD + k * 16, W6S_LD);
                wmma::load_matrix_sync(bl, sW6l + (wn * 32 + ni * 16) * W6S_LD + k * 16, W6S_LD);
#pragma unroll
                for (int mi = 0; mi < 2; mi++) {
                    wmma::mma_sync(c[mi][ni], ah[mi], bh, c[mi][ni]);
                    wmma::mma_sync(c[mi][ni], ah[mi], bl, c[mi][ni]);
                    wmma::mma_sync(c[mi][ni], al[mi], bh, c[mi][ni]);
                }
            }
        }
        __syncthreads();   // all warps done reading W6 chunk; Cbuf region free

        // store fp32 C piece (32x32), relu + split -> H (warp-local)
#pragma unroll
        for (int mi = 0; mi < 2; mi++)
#pragma unroll
            for (int ni = 0; ni < 2; ni++)
                wmma::store_matrix_sync(Cbuf + (wm * 32 + mi * 16) * CB_LD + wn * 32 + ni * 16,
                                        c[mi][ni], CB_LD, wmma::mem_row_major);
        __syncwarp();
#pragma unroll
        for (int idx = 0; idx < 32; idx++) {
            int f = lane + idx * 32;           // 0..1023 : 32 rows x 32 cols
            int r = f >> 5, cc = f & 31;
            float v = fmaxf(Cbuf[(wm * 32 + r) * CB_LD + wn * 32 + cc], 0.f);
            __nv_bfloat16 h, l;
            bf16_split(v, h, l);
            sHh[(wm * 32 + r) * HS_LD + wn * 32 + cc] = h;
            sHl[(wm * 32 + r) * HS_LD + wn * 32 + cc] = l;
        }
        __syncthreads();   // H chunk complete (GEMM2 A spans both wn halves)

        // GEMM2 partial: warp w -> rows w*16; ea[n] over N=32
#pragma unroll
        for (int k2 = 0; k2 < 4; k2++) {
            wmma::fragment<wmma::matrix_a, 16, 16, 16, __nv_bfloat16, wmma::row_major> ah, al;
            wmma::load_matrix_sync(ah, sHh + w * 16 * HS_LD + k2 * 16, HS_LD);
            wmma::load_matrix_sync(al, sHl + w * 16 * HS_LD + k2 * 16, HS_LD);
#pragma unroll
            for (int n = 0; n < 2; n++) {
                wmma::fragment<wmma::matrix_b, 16, 16, 16, __nv_bfloat16, wmma::col_major> bh, bl;
                wmma::load_matrix_sync(bh, sW7h + n * 16 * W7S_LD + k2 * 16, W7S_LD);
                wmma::load_matrix_sync(bl, sW7l + n * 16 * W7S_LD + k2 * 16, W7S_LD);
                wmma::mma_sync(ea[n], ah, bh, ea[n]);
                wmma::mma_sync(ea[n], ah, bl, ea[n]);
                wmma::mma_sync(ea[n], al, bh, ea[n]);
            }
        }
    }

    // epilogue
    __syncthreads();
    float* Ebuf = Cbuf;                        // 64 x 36 fp32
    wmma::store_matrix_sync(Ebuf + w * 16 * EB_LD, ea[0], EB_LD, wmma::mem_row_major);
    wmma::store_matrix_sync(Ebuf + w * 16 * EB_LD + 16, ea[1], EB_LD, wmma::mem_row_major);
    __syncthreads();
    for (int f = t; f < FM * 8; f += 128) {    // 64 rows x 8 float4
        int r = f >> 3, sgi = f & 7;
        float4 v = *(float4*)&Ebuf[r * EB_LD + sgi * 4];
        *(float4*)&EA[((size_t)tile * FM + r) * KOUT + sgi * 4] = v;
    }
}

// ---------------- aggregation + output ----------------
__global__ void k_agg(const float* __restrict__ x, const int* __restrict__ ei,
                      const float* __restrict__ EA) {
    int i = blockIdx.x;
    int t = threadIdx.x;  // 256
    __shared__ float ea_b[8][33];
    __shared__ float x_b[8][64];
    __shared__ int elist[8], dlist[8];
    float acc[8];
#pragma unroll
    for (int q = 0; q < 8; q++) acc[q] = 0.f;
    int start = i * ROWCAP;
    int end = start + g_rowcnt[i];
    int c = t & 63, k0 = t >> 6;
    for (int p = start; p < end; p += 8) {
        int nb = min(8, end - p);
        if (t < nb) {
            int pk = g_rowedges[p + t];
            elist[t] = pk & 0x7FFF;
            dlist[t] = pk >> 15;
        }
        __syncthreads();
        for (int i2 = t; i2 < nb * 96; i2 += 256) {
            int b = i2 / 96, f = i2 % 96;
            if (f < 32) ea_b[b][f] = EA[(size_t)elist[b] * KOUT + f];
            else x_b[b][f - 32] = x[dlist[b] * DIN + f - 32];
        }
        __syncthreads();
        for (int b = 0; b < nb; b++) {
            float xv = x_b[b][c];
#pragma unroll
            for (int q = 0; q < 8; q++) acc[q] += ea_b[b][k0 + q * 4] * xv;
        }
        __syncthreads();
    }
#pragma unroll
    for (int q = 0; q < 8; q++) g_AGG[i * (KOUT * DIN) + t + q * 256] = acc[q];
}

__global__ void k_out(const float* __restrict__ CW, const float* __restrict__ CB,
                      float* __restrict__ xout) {
    __shared__ float As[32][32];
    __shared__ float Bs[32][68];
    int t = threadIdx.x;
    int tx = t & 15, ty = t >> 4;
    int rowBase = blockIdx.x * 32;
    const int KTOT = KOUT * DIN;
    float acc[2][4] = {};
    for (int k0 = 0; k0 < KTOT; k0 += 32) {
        {
            int r = t >> 3, kk = (t & 7) << 2;
            float4 v = *(const float4*)&g_AGG[(rowBase + r) * KTOT + k0 + kk];
            *(float4*)&As[r][kk] = v;
        }
#pragma unroll
        for (int l = 0; l < 2; l++) {
            int fid = t + l * 256;
            int kk = fid >> 4, n4 = (fid & 15) << 2;
            float4 v = *(const float4*)&CW[(k0 + kk) * DOUT + n4];
            *(float4*)&Bs[kk][n4] = v;
        }
        __syncthreads();
#pragma unroll
        for (int kk = 0; kk < 32; kk++) {
            float a[2], b[4];
            a[0] = As[ty * 2][kk]; a[1] = As[ty * 2 + 1][kk];
            float4 bv = *(const float4*)&Bs[kk][tx * 4];
            b[0] = bv.x; b[1] = bv.y; b[2] = bv.z; b[3] = bv.w;
#pragma unroll
            for (int i = 0; i < 2; i++)
#pragma unroll
                for (int j = 0; j < 4; j++) acc[i][j] += a[i] * b[j];
        }
        __syncthreads();
    }
#pragma unroll
    for (int i = 0; i < 2; i++) {
        int r = rowBase + ty * 2 + i;
#pragma unroll
        for (int j = 0; j < 4; j++)
            xout[r * DOUT + tx * 4 + j] = acc[i][j] + CB[tx * 4 + j];
    }
}

// ---------------------------------------------------------------
extern "C" void kernel_launch(void* const* d_in, const int* in_sizes, int n_in,
                              void* d_out, int out_size) {
    const float* x     = (const float*)d_in[0];
    const int*   ei    = (const int*)  d_in[1];
    const float* SP    = (const float*)d_in[2];
    const float* Wnode = (const float*)d_in[4];
    const float* W2    = (const float*)d_in[5];
    const float* W3    = (const float*)d_in[6];
    const float* W4    = (const float*)d_in[7];
    const float* W5    = (const float*)d_in[8];
    const float* W6    = (const float*)d_in[9];
    const float* W7    = (const float*)d_in[10];
    const float* CW    = (const float*)d_in[11];
    const float* CB    = (const float*)d_in[12];

    float* xout = (float*)d_out;                       // [1024, 64]
    float* EA   = (float*)d_out + N_NODES * DOUT;      // [32768, 32]

    cudaFuncSetAttribute(k_fused, cudaFuncAttributeMaxDynamicSharedMemorySize, SMEM_FUSED);
    cudaFuncSetAttribute(k_edgex, cudaFuncAttributeMaxDynamicSharedMemorySize, SMEM_EDGEX);

    k_prep<<<NB_PREP, 512>>>(x, Wnode, W6, W7, W2, W3, W4, W5);   // 0
    k_edgex<<<N_TILES, 256, SMEM_EDGEX>>>(SP, ei);                // 1
    k_path<<<N_EDGES / 8, 256>>>(ei);                             // 2
    k_fused<<<FGRID, 128, SMEM_FUSED>>>(SP, ei, EA);              // 3
    k_agg<<<N_NODES, 256>>>(x, ei, EA);                           // 4
    k_out<<<N_NODES / 32, 256>>>(CW, CB, xout);                   // 5
}